// round 6
// baseline (speedup 1.0000x reference)
#include <cuda_runtime.h>
#include <cstdint>

#define NN   10000
#define BB   32
#define DIN  2
#define HH   64
#define GIN  66
#define CC   (GIN*BB)        // 2112
#define MHOP 3
#define KF   (GIN*MHOP)      // 198

#define S_A  500000.0f
#define S_X  32.0f
#define S_P  1024.0f
#define INV1 (1.0f/(S_A*S_X))      // gemm1 descale
#define INV2 (2.0f/(S_A*S_P))      // gemm2 descale incl. Chebyshev factor 2

#define KTILES 157                 // ceil(10000/64); 10000 = 156*64+16 (16B-chunk aligned)
#define STG    20480               // per stage: A 128*80 + B 128*80
#define FPITCH 204                 // feature tile pitch (bank-spread for tf32 frag loads)

// ------------------------- scratch (device globals; no allocation) -------------------------
__device__ int8_t g_Aq [(size_t)NN*NN];    // A * 5e5, int8 [m][k]
__device__ int8_t g_XqT[(size_t)CC*NN];    // hop-0 operand int8, transposed [c][node]
__device__ int8_t g_PqT[(size_t)CC*NN];    // hop-1 operand int8, transposed
__device__ float  g_Xf [(size_t)NN*CC];    // hop-0 fp32 [node][c], c = b*GIN+d
__device__ float  g_P1f[(size_t)NN*CC];    // hop-1 fp32
__device__ float  g_P2f[(size_t)NN*CC];    // hop-2 fp32
__device__ float  g_rs [(size_t)BB*NN*HH]; // r * states
__device__ float  g_u  [(size_t)BB*NN*HH]; // u gate

__device__ __forceinline__ int8_t q8(float x) {
    int v = __float2int_rn(x);
    v = min(127, max(-127, v));
    return (int8_t)v;
}

// ------------------------- A fp32 -> int8 -------------------------
__global__ void k_convertA(const float* __restrict__ A) {
    size_t i = ((size_t)blockIdx.x*blockDim.x + threadIdx.x)*4;
    if (i >= (size_t)NN*NN) return;
    float4 v = *(const float4*)(A + i);
    char4 c;
    c.x = q8(v.x*S_A); c.y = q8(v.y*S_A); c.z = q8(v.z*S_A); c.w = q8(v.w*S_A);
    *(char4*)(g_Aq + i) = c;
}

// ------------- build X = concat(inputs, s/r*s): fp32 [n][c] + int8 transposed [c][n] -------
__global__ __launch_bounds__(256) void k_buildX(const float* __restrict__ inputs,
                                                const float* __restrict__ st, int useRS) {
    __shared__ float sm[32][33];
    const int tx = threadIdx.x & 31, ty = threadIdx.x >> 5;   // ty 0..7
    const int c0 = blockIdx.x*32, n0 = blockIdx.y*32;
    const float* __restrict__ sp = useRS ? g_rs : st;
    const int c = c0 + tx;
    const int b = c / GIN, d = c % GIN;
    #pragma unroll
    for (int j = 0; j < 4; j++) {
        int nl = ty + j*8, n = n0 + nl;
        if (n < NN) {
            float v = (d < DIN) ? inputs[((size_t)b*NN + n)*DIN + d]
                                : sp[((size_t)b*NN + n)*HH + (d - DIN)];
            g_Xf[(size_t)n*CC + c] = v;
            sm[nl][tx] = v;
        }
    }
    __syncthreads();
    #pragma unroll
    for (int j = 0; j < 4; j++) {
        int cl = ty + j*8, n = n0 + tx;
        if (n < NN)
            g_XqT[(size_t)(c0 + cl)*NN + n] = q8(sm[tx][cl] * S_X);
    }
}

// ------------------------- big GEMM: int8 IMMA, 128x128x64 tiles, 4-stage cp.async --------
// mode 0: B = g_XqT -> g_P1f (fp32) + g_PqT (int8 T);  mode 1: B = g_PqT -> g_P2f = 2*acc*inv - Xf
__global__ __launch_bounds__(256, 2) void k_gemm(int mode)
{
    extern __shared__ char sm[];
    const int tid = threadIdx.x, lane = tid & 31, wid = tid >> 5;
    const int wm = wid >> 1, wn = wid & 1;               // 4x2 warps, 32x64 warp tile
    const int m0 = blockIdx.y*128, c0 = blockIdx.x*128;
    const int8_t* __restrict__ Bq = mode ? g_PqT : g_XqT;
    const uint32_t sb = (uint32_t)__cvta_generic_to_shared(sm);

    int acc[2][8][4];
    #pragma unroll
    for (int i = 0; i < 2; i++)
        #pragma unroll
        for (int j = 0; j < 8; j++)
            #pragma unroll
            for (int q = 0; q < 4; q++) acc[i][j][q] = 0;

    auto load = [&](int kt) {
        const int k0 = kt*64;
        const uint32_t base = sb + (kt & 3)*STG;
        #pragma unroll
        for (int qq = 0; qq < 4; qq++) {
            int i = tid + qq*256;
            const int8_t* gp; uint32_t dst; bool ok;
            if (i < 512) {                                // A: 128 rows x 4 16B chunks
                int r = i >> 2, ch = i & 3;
                gp  = g_Aq + (size_t)(m0 + r)*NN + k0 + ch*16;
                ok  = (m0 + r < NN) && (k0 + ch*16 < NN);
                dst = base + r*80 + ch*16;
            } else {                                      // B: 128 c-rows x 4 chunks
                int j = i - 512, r = j >> 2, ch = j & 3;
                gp  = Bq + (size_t)(c0 + r)*NN + k0 + ch*16;
                ok  = (c0 + r < CC) && (k0 + ch*16 < NN);
                dst = base + 10240 + r*80 + ch*16;
            }
            int bytes = ok ? 16 : 0;
            if (!ok) gp = g_Aq;
            asm volatile("cp.async.cg.shared.global [%0],[%1],16,%2;"
                         :: "r"(dst), "l"(gp), "r"(bytes));
        }
        asm volatile("cp.async.commit_group;" ::: "memory");
    };

    load(0); load(1); load(2);

    for (int kt = 0; kt < KTILES; kt++) {
        asm volatile("cp.async.wait_group 2;" ::: "memory");
        __syncthreads();
        if (kt + 3 < KTILES) load(kt + 3);
        else asm volatile("cp.async.commit_group;" ::: "memory");

        const uint32_t aS = sb + (kt & 3)*STG;
        const uint32_t bS = aS + 10240;
        #pragma unroll
        for (int kk = 0; kk < 2; kk++) {
            uint32_t a[2][4];
            #pragma unroll
            for (int mt = 0; mt < 2; mt++) {
                uint32_t ad = aS + (uint32_t)(wm*32 + mt*16 + (lane & 15))*80
                                 + (uint32_t)(kk*2 + (lane >> 4))*16;
                asm volatile("ldmatrix.sync.aligned.m8n8.x4.shared.b16 {%0,%1,%2,%3},[%4];"
                    : "=r"(a[mt][0]),"=r"(a[mt][1]),"=r"(a[mt][2]),"=r"(a[mt][3]) : "r"(ad));
            }
            uint32_t b[8][2];
            #pragma unroll
            for (int nj = 0; nj < 4; nj++) {
                uint32_t bd = bS + (uint32_t)(wn*64 + nj*16 + (lane & 7) + ((lane >> 4) << 3))*80
                                 + (uint32_t)(kk*2 + ((lane >> 3) & 1))*16;
                asm volatile("ldmatrix.sync.aligned.m8n8.x4.shared.b16 {%0,%1,%2,%3},[%4];"
                    : "=r"(b[2*nj][0]),"=r"(b[2*nj][1]),"=r"(b[2*nj+1][0]),"=r"(b[2*nj+1][1]) : "r"(bd));
            }
            #pragma unroll
            for (int mt = 0; mt < 2; mt++)
                #pragma unroll
                for (int ni = 0; ni < 8; ni++)
                    asm volatile("mma.sync.aligned.m16n8k32.row.col.s32.s8.s8.s32 "
                        "{%0,%1,%2,%3},{%4,%5,%6,%7},{%8,%9},{%0,%1,%2,%3};"
                        : "+r"(acc[mt][ni][0]),"+r"(acc[mt][ni][1]),
                          "+r"(acc[mt][ni][2]),"+r"(acc[mt][ni][3])
                        : "r"(a[mt][0]),"r"(a[mt][1]),"r"(a[mt][2]),"r"(a[mt][3]),
                          "r"(b[ni][0]),"r"(b[ni][1]));
        }
    }
    __syncthreads();                      // all warps done reading stage smem

    // ---- epilogue ----
    float* __restrict__ outF = mode ? g_P2f : g_P1f;
    int8_t* smT = (int8_t*)sm;            // [128 c][pitch 144] int8 transpose stage
    #pragma unroll
    for (int mt = 0; mt < 2; mt++)
        #pragma unroll
        for (int ni = 0; ni < 8; ni++) {
            int cl  = wn*64 + ni*8 + (lane & 3)*2;
            int col = c0 + cl;
            #pragma unroll
            for (int h = 0; h < 2; h++) {
                int rl  = wm*32 + mt*16 + (lane >> 2) + h*8;
                int row = m0 + rl;
                if (row < NN && col < CC) {
                    size_t o = (size_t)row*CC + col;
                    float v0, v1;
                    if (mode) {
                        v0 = acc[mt][ni][2*h  ]*INV2 - g_Xf[o];
                        v1 = acc[mt][ni][2*h+1]*INV2 - g_Xf[o+1];
                    } else {
                        v0 = acc[mt][ni][2*h  ]*INV1;
                        v1 = acc[mt][ni][2*h+1]*INV1;
                    }
                    outF[o] = v0; outF[o+1] = v1;
                    if (!mode) {
                        smT[(cl  )*144 + rl] = q8(v0*S_P);
                        smT[(cl+1)*144 + rl] = q8(v1*S_P);
                    }
                }
            }
        }
    if (!mode) {
        __syncthreads();
        for (int i = tid; i < 128*8; i += 256) {
            int cr = i >> 3, ch = i & 7;
            if (c0 + cr < CC && m0 + ch*16 < NN)
                *(uint4*)(g_PqT + (size_t)(c0 + cr)*NN + m0 + ch*16) =
                    *(const uint4*)(smT + cr*144 + ch*16);
        }
    }
}

// --------------- feature GEMM RU: (320000 x 198) @ (198 x 128), tf32 mma, fused gates ------
__global__ __launch_bounds__(256) void k_featRU(
    const float* __restrict__ Wru, const float* __restrict__ bru,
    const float* __restrict__ states)
{
    extern __shared__ float fsm[];
    float* wt = fsm + 128*FPITCH;                 // 2 x [128 col][12] W^T tiles
    const int tid = threadIdx.x, lane = tid & 31, wid = tid >> 5;
    const int wm = wid >> 1, wn = wid & 1;
    const int R0 = blockIdx.x*128;

    for (int i = tid; i < 128*200; i += 256) {    // F tile, k padded to 200
        int lr = i/200, k = i%200;
        float v = 0.f;
        if (k < KF) {
            int d = k/3, m = k%3;
            int R = R0 + lr, n = R >> 5, b = R & 31;
            const float* src = (m==0) ? g_Xf : (m==1) ? g_P1f : g_P2f;
            v = src[(size_t)n*CC + b*GIN + d];
        }
        uint32_t t; asm("cvt.rna.tf32.f32 %0,%1;" : "=r"(t) : "f"(v));
        fsm[lr*FPITCH + k] = __uint_as_float(t);
    }
    auto stageW = [&](int s, int buf) {
        for (int i = tid; i < 1024; i += 256) {
            int col = i & 127, kk = i >> 7, k = s*8 + kk;
            float v = (k < KF) ? Wru[k*128 + col] : 0.f;
            uint32_t t; asm("cvt.rna.tf32.f32 %0,%1;" : "=r"(t) : "f"(v));
            wt[buf*1536 + col*12 + kk] = __uint_as_float(t);
        }
    };
    stageW(0, 0);
    __syncthreads();

    float acc[2][8][4];
    #pragma unroll
    for (int i=0;i<2;i++) for (int j=0;j<8;j++) for (int q=0;q<4;q++) acc[i][j][q]=0.f;

    for (int s = 0; s < 25; s++) {
        if (s + 1 < 25) stageW(s + 1, (s + 1) & 1);
        const int kb = s*8 + (lane & 3);
        uint32_t a[2][4];
        #pragma unroll
        for (int mt = 0; mt < 2; mt++) {
            int rA = wm*32 + mt*16 + (lane >> 2);
            a[mt][0] = __float_as_uint(fsm[ rA     *FPITCH + kb  ]);
            a[mt][1] = __float_as_uint(fsm[(rA + 8)*FPITCH + kb  ]);
            a[mt][2] = __float_as_uint(fsm[ rA     *FPITCH + kb+4]);
            a[mt][3] = __float_as_uint(fsm[(rA + 8)*FPITCH + kb+4]);
        }
        const float* wb = wt + (s & 1)*1536;
        #pragma unroll
        for (int t8 = 0; t8 < 8; t8++) {
            int colb = wn*64 + t8*8 + (lane >> 2);
            uint32_t b0 = __float_as_uint(wb[colb*12 + (lane & 3)    ]);
            uint32_t b1 = __float_as_uint(wb[colb*12 + (lane & 3) + 4]);
            #pragma unroll
            for (int mt = 0; mt < 2; mt++)
                asm volatile("mma.sync.aligned.m16n8k8.row.col.f32.tf32.tf32.f32 "
                    "{%0,%1,%2,%3},{%4,%5,%6,%7},{%8,%9},{%0,%1,%2,%3};"
                    : "+f"(acc[mt][t8][0]),"+f"(acc[mt][t8][1]),
                      "+f"(acc[mt][t8][2]),"+f"(acc[mt][t8][3])
                    : "r"(a[mt][0]),"r"(a[mt][1]),"r"(a[mt][2]),"r"(a[mt][3]),
                      "r"(b0),"r"(b1));
        }
        __syncthreads();
    }

    #pragma unroll
    for (int mt = 0; mt < 2; mt++)
        #pragma unroll
        for (int t8 = 0; t8 < 8; t8++) {
            int col = wn*64 + t8*8 + (lane & 3)*2;
            #pragma unroll
            for (int h = 0; h < 2; h++) {
                int rl = wm*32 + mt*16 + (lane >> 2) + h*8;
                int R = R0 + rl, n = R >> 5, b = R & 31;
                #pragma unroll
                for (int e = 0; e < 2; e++) {
                    int o = col + e;
                    float z = acc[mt][t8][2*h + e] + bru[o];
                    float sg = 1.f/(1.f + __expf(-z));
                    if (o < HH) {
                        size_t oi = ((size_t)b*NN + n)*HH + o;
                        g_rs[oi] = sg * states[oi];
                    } else {
                        g_u[((size_t)b*NN + n)*HH + o - HH] = sg;
                    }
                }
            }
        }
}

// --------------- feature GEMM C: (320000 x 198) @ (198 x 64), tf32 mma, final gate ---------
__global__ __launch_bounds__(256) void k_featC(
    const float* __restrict__ Wc, const float* __restrict__ bc,
    const float* __restrict__ states, float* __restrict__ out)
{
    extern __shared__ float fsm[];
    float* wt = fsm + 128*FPITCH;                 // 2 x [64 col][12]
    const int tid = threadIdx.x, lane = tid & 31, wid = tid >> 5;
    const int wm = wid >> 1, wn = wid & 1;
    const int R0 = blockIdx.x*128;

    for (int i = tid; i < 128*200; i += 256) {
        int lr = i/200, k = i%200;
        float v = 0.f;
        if (k < KF) {
            int d = k/3, m = k%3;
            int R = R0 + lr, n = R >> 5, b = R & 31;
            const float* src = (m==0) ? g_Xf : (m==1) ? g_P1f : g_P2f;
            v = src[(size_t)n*CC + b*GIN + d];
        }
        uint32_t t; asm("cvt.rna.tf32.f32 %0,%1;" : "=r"(t) : "f"(v));
        fsm[lr*FPITCH + k] = __uint_as_float(t);
    }
    auto stageW = [&](int s, int buf) {
        for (int i = tid; i < 512; i += 256) {
            int col = i & 63, kk = i >> 6, k = s*8 + kk;
            float v = (k < KF) ? Wc[k*64 + col] : 0.f;
            uint32_t t; asm("cvt.rna.tf32.f32 %0,%1;" : "=r"(t) : "f"(v));
            wt[buf*768 + col*12 + kk] = __uint_as_float(t);
        }
    };
    stageW(0, 0);
    __syncthreads();

    float acc[2][4][4];
    #pragma unroll
    for (int i=0;i<2;i++) for (int j=0;j<4;j++) for (int q=0;q<4;q++) acc[i][j][q]=0.f;

    for (int s = 0; s < 25; s++) {
        if (s + 1 < 25) stageW(s + 1, (s + 1) & 1);
        const int kb = s*8 + (lane & 3);
        uint32_t a[2][4];
        #pragma unroll
        for (int mt = 0; mt < 2; mt++) {
            int rA = wm*32 + mt*16 + (lane >> 2);
            a[mt][0] = __float_as_uint(fsm[ rA     *FPITCH + kb  ]);
            a[mt][1] = __float_as_uint(fsm[(rA + 8)*FPITCH + kb  ]);
            a[mt][2] = __float_as_uint(fsm[ rA     *FPITCH + kb+4]);
            a[mt][3] = __float_as_uint(fsm[(rA + 8)*FPITCH + kb+4]);
        }
        const float* wb = wt + (s & 1)*768;
        #pragma unroll
        for (int t8 = 0; t8 < 4; t8++) {
            int colb = wn*32 + t8*8 + (lane >> 2);
            uint32_t b0 = __float_as_uint(wb[colb*12 + (lane & 3)    ]);
            uint32_t b1 = __float_as_uint(wb[colb*12 + (lane & 3) + 4]);
            #pragma unroll
            for (int mt = 0; mt < 2; mt++)
                asm volatile("mma.sync.aligned.m16n8k8.row.col.f32.tf32.tf32.f32 "
                    "{%0,%1,%2,%3},{%4,%5,%6,%7},{%8,%9},{%0,%1,%2,%3};"
                    : "+f"(acc[mt][t8][0]),"+f"(acc[mt][t8][1]),
                      "+f"(acc[mt][t8][2]),"+f"(acc[mt][t8][3])
                    : "r"(a[mt][0]),"r"(a[mt][1]),"r"(a[mt][2]),"r"(a[mt][3]),
                      "r"(b0),"r"(b1));
        }
        __syncthreads();
    }

    #pragma unroll
    for (int mt = 0; mt < 2; mt++)
        #pragma unroll
        for (int t8 = 0; t8 < 4; t8++) {
            int col = wn*32 + t8*8 + (lane & 3)*2;
            #pragma unroll
            for (int h = 0; h < 2; h++) {
                int rl = wm*32 + mt*16 + (lane >> 2) + h*8;
                int R = R0 + rl, n = R >> 5, b = R & 31;
                #pragma unroll
                for (int e = 0; e < 2; e++) {
                    int o = col + e;
                    float cz = tanhf(acc[mt][t8][2*h + e] + bc[o]);
                    size_t oi = ((size_t)b*NN + n)*HH + o;
                    float u = g_u[oi];
                    out[oi] = u*states[oi] + (1.f - u)*cz;
                }
            }
        }
}

// ------------------------- launch -------------------------
extern "C" void kernel_launch(void* const* d_in, const int* in_sizes, int n_in,
                              void* d_out, int out_size) {
    const float* inputs = (const float*)d_in[0];
    const float* states = (const float*)d_in[1];
    const float* A      = (const float*)d_in[2];
    const float* W_ru   = (const float*)d_in[3];
    const float* b_ru   = (const float*)d_in[4];
    const float* W_c    = (const float*)d_in[5];
    const float* b_c    = (const float*)d_in[6];
    float* out = (float*)d_out;

    static int inited = 0;
    const int gemmSmem = 4*STG;                          // 81920
    const int ruSmem   = 128*FPITCH*4 + 2*1536*4;        // 116736
    const int cSmem    = 128*FPITCH*4 + 2*768*4;         // 110592
    if (!inited) {
        cudaFuncSetAttribute(k_gemm,   cudaFuncAttributeMaxDynamicSharedMemorySize, gemmSmem);
        cudaFuncSetAttribute(k_featRU, cudaFuncAttributeMaxDynamicSharedMemorySize, ruSmem);
        cudaFuncSetAttribute(k_featC,  cudaFuncAttributeMaxDynamicSharedMemorySize, cSmem);
        inited = 1;
    }

    dim3 gemmGrid((CC + 127)/128, (NN + 127)/128);       // 17 x 79
    dim3 buildGrid(CC/32, (NN + 31)/32);                 // 66 x 313
    const int featGrid = (NN*BB)/128;                    // 2500

    k_convertA<<<(int)(((size_t)NN*NN/4 + 255)/256), 256>>>(A);

    // gconv 1: x = [inputs, states]
    k_buildX<<<buildGrid, 256>>>(inputs, states, 0);
    k_gemm<<<gemmGrid, 256, gemmSmem>>>(0);              // P1 = A @ X
    k_gemm<<<gemmGrid, 256, gemmSmem>>>(1);              // P2 = 2 A @ P1 - X
    k_featRU<<<featGrid, 256, ruSmem>>>(W_ru, b_ru, states);

    // gconv 2: x = [inputs, r*states]
    k_buildX<<<buildGrid, 256>>>(inputs, states, 1);
    k_gemm<<<gemmGrid, 256, gemmSmem>>>(0);              // Q1
    k_gemm<<<gemmGrid, 256, gemmSmem>>>(1);              // Q2
    k_featC<<<featGrid, 256, cSmem>>>(W_c, b_c, states, out);
}

// round 7
// speedup vs baseline: 3.0678x; 3.0678x over previous
#include <cuda_runtime.h>
#include <cuda_bf16.h>
#include <cstdint>

#define NN   10000
#define BB   32
#define DIN  2
#define HH   64
#define GIN  66
#define CC   (GIN*BB)        // 2112
#define MHOP 3
#define KF   (GIN*MHOP)      // 198

#define BK     64
#define KTILES 157                 // ceil(10000/64)
#define ASTRIDE 72                 // 64 + 8 pad (bf16 elems)
#define BSTRIDE 136                // 128 + 8 pad
#define STG    ((128*ASTRIDE + BK*BSTRIDE)*2)   // 18432 + 17408 = 35840 B
#define GSMEM  (3*STG)                          // 107520
#define FPITCH 204

// ------------------------- scratch (device globals; no allocation) -------------------------
__device__ __nv_bfloat16 g_Abf[(size_t)NN*NN];   // bf16 A [m][k]
__device__ __nv_bfloat16 g_Xbf[(size_t)NN*CC];   // hop-0 operand bf16 [node][c]
__device__ __nv_bfloat16 g_Pbf[(size_t)NN*CC];   // hop-1 operand bf16 [node][c]
__device__ float g_Xf [(size_t)NN*CC];           // hop-0 fp32 [node][c], c = b*GIN+d
__device__ float g_P1f[(size_t)NN*CC];           // hop-1 fp32
__device__ float g_P2f[(size_t)NN*CC];           // hop-2 fp32
__device__ float g_rs [(size_t)BB*NN*HH];        // r * states
__device__ float g_u  [(size_t)BB*NN*HH];        // u gate

// ------------------------- A fp32 -> bf16 -------------------------
__global__ void k_convertA(const float* __restrict__ A) {
    size_t i = ((size_t)blockIdx.x*blockDim.x + threadIdx.x)*4;
    if (i >= (size_t)NN*NN) return;
    float4 v = *(const float4*)(A + i);
    ((__nv_bfloat162*)(g_Abf + i))[0] = __float22bfloat162_rn(make_float2(v.x, v.y));
    ((__nv_bfloat162*)(g_Abf + i))[1] = __float22bfloat162_rn(make_float2(v.z, v.w));
}

// ------------------------- build X = concat(inputs, s or r*s), c = b*GIN+d ----------------
__global__ void k_buildX(const float* __restrict__ inputs, const float* __restrict__ st, int useRS) {
    int idx = blockIdx.x*blockDim.x + threadIdx.x;
    if (idx >= NN*CC) return;
    int n = idx / CC, c = idx % CC;
    int b = c / GIN, d = c % GIN;
    const float* __restrict__ sp = useRS ? g_rs : st;
    float v = (d < DIN) ? inputs[((size_t)b*NN + n)*DIN + d]
                        : sp[((size_t)b*NN + n)*HH + (d - DIN)];
    g_Xf [idx] = v;
    g_Xbf[idx] = __float2bfloat16(v);
}

// -------- big GEMM: bf16 HMMA, 128x128x64 tiles, 3-stage cp.async, 1 sync/iter ------------
// mode 0: B = g_Xbf -> g_P1f (fp32) + g_Pbf (bf16);  mode 1: B = g_Pbf -> g_P2f = 2*acc - g_Xf
__global__ __launch_bounds__(256, 2) void k_gemm(int mode)
{
    extern __shared__ char sm[];
    const int tid = threadIdx.x, lane = tid & 31, wid = tid >> 5;
    const int wm = wid >> 1, wn = wid & 1;              // 4x2 warps, 32x64 warp tile
    const int m0 = blockIdx.y*128, c0 = blockIdx.x*128;
    const __nv_bfloat16* __restrict__ Bq = mode ? g_Pbf : g_Xbf;
    const uint32_t sb = (uint32_t)__cvta_generic_to_shared(sm);

    float acc[2][8][4];
    #pragma unroll
    for (int i = 0; i < 2; i++)
        #pragma unroll
        for (int j = 0; j < 8; j++)
            #pragma unroll
            for (int q = 0; q < 4; q++) acc[i][j][q] = 0.f;

    auto load = [&](int kt) {
        const int k0 = kt*BK;
        const uint32_t base = sb + (kt % 3)*STG;
        #pragma unroll
        for (int qq = 0; qq < 8; qq++) {
            int i = tid + qq*256;
            const __nv_bfloat16* gp; uint32_t dst; bool ok;
            if (i < 1024) {                               // A: 128 rows x 8 16B chunks
                int r = i >> 3, ch = i & 7;
                gp  = g_Abf + (size_t)(m0 + r)*NN + k0 + ch*8;
                ok  = (m0 + r < NN) && (k0 + ch*8 < NN);
                dst = base + (uint32_t)(r*ASTRIDE + ch*8)*2;
            } else {                                      // B: 64 k-rows x 16 chunks
                int j = i - 1024, r = j >> 4, ch = j & 15;
                gp  = Bq + (size_t)(k0 + r)*CC + c0 + ch*8;
                ok  = (k0 + r < NN) && (c0 + ch*8 < CC);
                dst = base + 128u*ASTRIDE*2 + (uint32_t)(r*BSTRIDE + ch*8)*2;
            }
            int bytes = ok ? 16 : 0;
            if (!ok) gp = g_Abf;
            asm volatile("cp.async.cg.shared.global [%0],[%1],16,%2;"
                         :: "r"(dst), "l"(gp), "r"(bytes));
        }
        asm volatile("cp.async.commit_group;" ::: "memory");
    };

    load(0); load(1);

    for (int kt = 0; kt < KTILES; kt++) {
        asm volatile("cp.async.wait_group 1;" ::: "memory");
        __syncthreads();
        // prefetch stage kt+2 into buffer (kt+2)%3 = (kt-1)%3 (freed by the sync above)
        if (kt + 2 < KTILES) load(kt + 2);
        else asm volatile("cp.async.commit_group;" ::: "memory");

        const uint32_t aS = sb + (kt % 3)*STG;
        const uint32_t bS = aS + 128u*ASTRIDE*2;
        #pragma unroll
        for (int kk = 0; kk < 4; kk++) {
            uint32_t a[2][4];
            #pragma unroll
            for (int mt = 0; mt < 2; mt++) {
                uint32_t ad = aS + (uint32_t)((wm*32 + mt*16 + (lane & 15))*ASTRIDE
                                              + kk*16 + (lane >> 4)*8)*2;
                asm volatile("ldmatrix.sync.aligned.m8n8.x4.shared.b16 {%0,%1,%2,%3},[%4];"
                    : "=r"(a[mt][0]),"=r"(a[mt][1]),"=r"(a[mt][2]),"=r"(a[mt][3]) : "r"(ad));
            }
            uint32_t b[8][2];
            #pragma unroll
            for (int nj = 0; nj < 4; nj++) {
                uint32_t bd = bS + (uint32_t)((kk*16 + (lane & 15))*BSTRIDE
                                              + wn*64 + nj*16 + (lane >> 4)*8)*2;
                asm volatile("ldmatrix.sync.aligned.m8n8.x4.trans.shared.b16 {%0,%1,%2,%3},[%4];"
                    : "=r"(b[2*nj][0]),"=r"(b[2*nj][1]),"=r"(b[2*nj+1][0]),"=r"(b[2*nj+1][1]) : "r"(bd));
            }
            #pragma unroll
            for (int mt = 0; mt < 2; mt++)
                #pragma unroll
                for (int ni = 0; ni < 8; ni++)
                    asm volatile("mma.sync.aligned.m16n8k16.row.col.f32.bf16.bf16.f32 "
                        "{%0,%1,%2,%3},{%4,%5,%6,%7},{%8,%9},{%0,%1,%2,%3};"
                        : "+f"(acc[mt][ni][0]),"+f"(acc[mt][ni][1]),
                          "+f"(acc[mt][ni][2]),"+f"(acc[mt][ni][3])
                        : "r"(a[mt][0]),"r"(a[mt][1]),"r"(a[mt][2]),"r"(a[mt][3]),
                          "r"(b[ni][0]),"r"(b[ni][1]));
        }
    }

    // ---- epilogue ----
    float* __restrict__ outF = mode ? g_P2f : g_P1f;
    #pragma unroll
    for (int mt = 0; mt < 2; mt++)
        #pragma unroll
        for (int ni = 0; ni < 8; ni++) {
            int col = c0 + wn*64 + ni*8 + (lane & 3)*2;
            #pragma unroll
            for (int h = 0; h < 2; h++) {
                int row = m0 + wm*32 + mt*16 + (lane >> 2) + h*8;
                if (row < NN && col < CC) {
                    size_t o = (size_t)row*CC + col;
                    float v0 = acc[mt][ni][2*h], v1 = acc[mt][ni][2*h+1];
                    if (mode) {
                        v0 = 2.f*v0 - g_Xf[o];
                        v1 = 2.f*v1 - g_Xf[o+1];
                    }
                    outF[o] = v0; outF[o+1] = v1;
                    if (!mode)
                        *(__nv_bfloat162*)(g_Pbf + o) =
                            __float22bfloat162_rn(make_float2(v0, v1));
                }
            }
        }
}

// --------------- feature GEMM RU: (320000 x 198) @ (198 x 128), tf32 mma, fused gates ------
__global__ __launch_bounds__(256) void k_featRU(
    const float* __restrict__ Wru, const float* __restrict__ bru,
    const float* __restrict__ states)
{
    extern __shared__ float fsm[];
    float* wt = fsm + 128*FPITCH;
    const int tid = threadIdx.x, lane = tid & 31, wid = tid >> 5;
    const int wm = wid >> 1, wn = wid & 1;
    const int R0 = blockIdx.x*128;

    for (int i = tid; i < 128*200; i += 256) {
        int lr = i/200, k = i%200;
        float v = 0.f;
        if (k < KF) {
            int d = k/3, m = k%3;
            int R = R0 + lr, n = R >> 5, b = R & 31;
            const float* src = (m==0) ? g_Xf : (m==1) ? g_P1f : g_P2f;
            v = src[(size_t)n*CC + b*GIN + d];
        }
        uint32_t t; asm("cvt.rna.tf32.f32 %0,%1;" : "=r"(t) : "f"(v));
        fsm[lr*FPITCH + k] = __uint_as_float(t);
    }
    auto stageW = [&](int s, int buf) {
        for (int i = tid; i < 1024; i += 256) {
            int col = i & 127, kk = i >> 7, k = s*8 + kk;
            float v = (k < KF) ? Wru[k*128 + col] : 0.f;
            uint32_t t; asm("cvt.rna.tf32.f32 %0,%1;" : "=r"(t) : "f"(v));
            wt[buf*1536 + col*12 + kk] = __uint_as_float(t);
        }
    };
    stageW(0, 0);
    __syncthreads();

    float acc[2][8][4];
    #pragma unroll
    for (int i=0;i<2;i++) for (int j=0;j<8;j++) for (int q=0;q<4;q++) acc[i][j][q]=0.f;

    for (int s = 0; s < 25; s++) {
        if (s + 1 < 25) stageW(s + 1, (s + 1) & 1);
        const int kb = s*8 + (lane & 3);
        uint32_t a[2][4];
        #pragma unroll
        for (int mt = 0; mt < 2; mt++) {
            int rA = wm*32 + mt*16 + (lane >> 2);
            a[mt][0] = __float_as_uint(fsm[ rA     *FPITCH + kb  ]);
            a[mt][1] = __float_as_uint(fsm[(rA + 8)*FPITCH + kb  ]);
            a[mt][2] = __float_as_uint(fsm[ rA     *FPITCH + kb+4]);
            a[mt][3] = __float_as_uint(fsm[(rA + 8)*FPITCH + kb+4]);
        }
        const float* wb = wt + (s & 1)*1536;
        #pragma unroll
        for (int t8 = 0; t8 < 8; t8++) {
            int colb = wn*64 + t8*8 + (lane >> 2);
            uint32_t b0 = __float_as_uint(wb[colb*12 + (lane & 3)    ]);
            uint32_t b1 = __float_as_uint(wb[colb*12 + (lane & 3) + 4]);
            #pragma unroll
            for (int mt = 0; mt < 2; mt++)
                asm volatile("mma.sync.aligned.m16n8k8.row.col.f32.tf32.tf32.f32 "
                    "{%0,%1,%2,%3},{%4,%5,%6,%7},{%8,%9},{%0,%1,%2,%3};"
                    : "+f"(acc[mt][t8][0]),"+f"(acc[mt][t8][1]),
                      "+f"(acc[mt][t8][2]),"+f"(acc[mt][t8][3])
                    : "r"(a[mt][0]),"r"(a[mt][1]),"r"(a[mt][2]),"r"(a[mt][3]),
                      "r"(b0),"r"(b1));
        }
        __syncthreads();
    }

    #pragma unroll
    for (int mt = 0; mt < 2; mt++)
        #pragma unroll
        for (int t8 = 0; t8 < 8; t8++) {
            int col = wn*64 + t8*8 + (lane & 3)*2;
            #pragma unroll
            for (int h = 0; h < 2; h++) {
                int rl = wm*32 + mt*16 + (lane >> 2) + h*8;
                int R = R0 + rl, n = R >> 5, b = R & 31;
                #pragma unroll
                for (int e = 0; e < 2; e++) {
                    int o = col + e;
                    float z = acc[mt][t8][2*h + e] + bru[o];
                    float sg = 1.f/(1.f + __expf(-z));
                    if (o < HH) {
                        size_t oi = ((size_t)b*NN + n)*HH + o;
                        g_rs[oi] = sg * states[oi];
                    } else {
                        g_u[((size_t)b*NN + n)*HH + o - HH] = sg;
                    }
                }
            }
        }
}

// --------------- feature GEMM C: (320000 x 198) @ (198 x 64), tf32 mma, final gate ---------
__global__ __launch_bounds__(256) void k_featC(
    const float* __restrict__ Wc, const float* __restrict__ bc,
    const float* __restrict__ states, float* __restrict__ out)
{
    extern __shared__ float fsm[];
    float* wt = fsm + 128*FPITCH;
    const int tid = threadIdx.x, lane = tid & 31, wid = tid >> 5;
    const int wm = wid >> 1, wn = wid & 1;
    const int R0 = blockIdx.x*128;

    for (int i = tid; i < 128*200; i += 256) {
        int lr = i/200, k = i%200;
        float v = 0.f;
        if (k < KF) {
            int d = k/3, m = k%3;
            int R = R0 + lr, n = R >> 5, b = R & 31;
            const float* src = (m==0) ? g_Xf : (m==1) ? g_P1f : g_P2f;
            v = src[(size_t)n*CC + b*GIN + d];
        }
        uint32_t t; asm("cvt.rna.tf32.f32 %0,%1;" : "=r"(t) : "f"(v));
        fsm[lr*FPITCH + k] = __uint_as_float(t);
    }
    auto stageW = [&](int s, int buf) {
        for (int i = tid; i < 512; i += 256) {
            int col = i & 63, kk = i >> 6, k = s*8 + kk;
            float v = (k < KF) ? Wc[k*64 + col] : 0.f;
            uint32_t t; asm("cvt.rna.tf32.f32 %0,%1;" : "=r"(t) : "f"(v));
            wt[buf*768 + col*12 + kk] = __uint_as_float(t);
        }
    };
    stageW(0, 0);
    __syncthreads();

    float acc[2][4][4];
    #pragma unroll
    for (int i=0;i<2;i++) for (int j=0;j<4;j++) for (int q=0;q<4;q++) acc[i][j][q]=0.f;

    for (int s = 0; s < 25; s++) {
        if (s + 1 < 25) stageW(s + 1, (s + 1) & 1);
        const int kb = s*8 + (lane & 3);
        uint32_t a[2][4];
        #pragma unroll
        for (int mt = 0; mt < 2; mt++) {
            int rA = wm*32 + mt*16 + (lane >> 2);
            a[mt][0] = __float_as_uint(fsm[ rA     *FPITCH + kb  ]);
            a[mt][1] = __float_as_uint(fsm[(rA + 8)*FPITCH + kb  ]);
            a[mt][2] = __float_as_uint(fsm[ rA     *FPITCH + kb+4]);
            a[mt][3] = __float_as_uint(fsm[(rA + 8)*FPITCH + kb+4]);
        }
        const float* wb = wt + (s & 1)*768;
        #pragma unroll
        for (int t8 = 0; t8 < 4; t8++) {
            int colb = wn*32 + t8*8 + (lane >> 2);
            uint32_t b0 = __float_as_uint(wb[colb*12 + (lane & 3)    ]);
            uint32_t b1 = __float_as_uint(wb[colb*12 + (lane & 3) + 4]);
            #pragma unroll
            for (int mt = 0; mt < 2; mt++)
                asm volatile("mma.sync.aligned.m16n8k8.row.col.f32.tf32.tf32.f32 "
                    "{%0,%1,%2,%3},{%4,%5,%6,%7},{%8,%9},{%0,%1,%2,%3};"
                    : "+f"(acc[mt][t8][0]),"+f"(acc[mt][t8][1]),
                      "+f"(acc[mt][t8][2]),"+f"(acc[mt][t8][3])
                    : "r"(a[mt][0]),"r"(a[mt][1]),"r"(a[mt][2]),"r"(a[mt][3]),
                      "r"(b0),"r"(b1));
        }
        __syncthreads();
    }

    #pragma unroll
    for (int mt = 0; mt < 2; mt++)
        #pragma unroll
        for (int t8 = 0; t8 < 4; t8++) {
            int col = wn*32 + t8*8 + (lane & 3)*2;
            #pragma unroll
            for (int h = 0; h < 2; h++) {
                int rl = wm*32 + mt*16 + (lane >> 2) + h*8;
                int R = R0 + rl, n = R >> 5, b = R & 31;
                #pragma unroll
                for (int e = 0; e < 2; e++) {
                    int o = col + e;
                    float cz = tanhf(acc[mt][t8][2*h + e] + bc[o]);
                    size_t oi = ((size_t)b*NN + n)*HH + o;
                    float u = g_u[oi];
                    out[oi] = u*states[oi] + (1.f - u)*cz;
                }
            }
        }
}

// ------------------------- launch -------------------------
extern "C" void kernel_launch(void* const* d_in, const int* in_sizes, int n_in,
                              void* d_out, int out_size) {
    const float* inputs = (const float*)d_in[0];
    const float* states = (const float*)d_in[1];
    const float* A      = (const float*)d_in[2];
    const float* W_ru   = (const float*)d_in[3];
    const float* b_ru   = (const float*)d_in[4];
    const float* W_c    = (const float*)d_in[5];
    const float* b_c    = (const float*)d_in[6];
    float* out = (float*)d_out;

    static int inited = 0;
    const int ruSmem = 128*FPITCH*4 + 2*1536*4;      // 116736
    const int cSmem  = 128*FPITCH*4 + 2*768*4;       // 110592
    if (!inited) {
        cudaFuncSetAttribute(k_gemm,   cudaFuncAttributeMaxDynamicSharedMemorySize, GSMEM);
        cudaFuncSetAttribute(k_featRU, cudaFuncAttributeMaxDynamicSharedMemorySize, ruSmem);
        cudaFuncSetAttribute(k_featC,  cudaFuncAttributeMaxDynamicSharedMemorySize, cSmem);
        inited = 1;
    }

    dim3 gemmGrid((CC + 127)/128, (NN + 127)/128);   // 17 x 79
    const int featGrid = (NN*BB)/128;                // 2500

    k_convertA<<<(int)(((size_t)NN*NN/4 + 255)/256), 256>>>(A);

    // gconv 1: x = [inputs, states]
    k_buildX<<<(NN*CC + 255)/256, 256>>>(inputs, states, 0);
    k_gemm<<<gemmGrid, 256, GSMEM>>>(0);             // P1 = A @ X
    k_gemm<<<gemmGrid, 256, GSMEM>>>(1);             // P2 = 2 A @ P1 - X
    k_featRU<<<featGrid, 256, ruSmem>>>(W_ru, b_ru, states);

    // gconv 2: x = [inputs, r*states]
    k_buildX<<<(NN*CC + 255)/256, 256>>>(inputs, states, 1);
    k_gemm<<<gemmGrid, 256, GSMEM>>>(0);             // Q1
    k_gemm<<<gemmGrid, 256, GSMEM>>>(1);             // Q2
    k_featC<<<featGrid, 256, cSmem>>>(W_c, b_c, states, out);
}

// round 10
// speedup vs baseline: 3.2367x; 1.0551x over previous
#include <cuda_runtime.h>
#include <cuda_bf16.h>
#include <cstdint>

#define NN   10000
#define BB   32
#define DIN  2
#define HH   64
#define GIN  66
#define CC   (GIN*BB)        // 2112
#define MHOP 3
#define KF   (GIN*MHOP)      // 198

#define BM     256
#define BN     128
#define BK     64
#define KTILES 157                 // ceil(10000/64)
#define ASTRIDE 72                 // 64 + 8 pad (bf16 elems)
#define BSTRIDE 136                // 128 + 8 pad
#define ABYTES (BM*ASTRIDE*2)      // 36864
#define STG    (ABYTES + BK*BSTRIDE*2)   // 36864 + 17408 = 54272
#define GSMEM  (3*STG)                   // 162816

// ------------------------- scratch (device globals; no allocation) -------------------------
__device__ __nv_bfloat16 g_Abf[(size_t)NN*NN];   // bf16 A [m][k]
__device__ __nv_bfloat16 g_Xbf[(size_t)NN*CC];   // hop-0 operand bf16 [node][c], c=d*32+b
__device__ __nv_bfloat16 g_Pbf[(size_t)NN*CC];   // hop-1 operand bf16
__device__ float g_Xf [(size_t)NN*CC];           // hop-0 fp32
__device__ float g_P1f[(size_t)NN*CC];           // hop-1 fp32
__device__ float g_P2f[(size_t)NN*CC];           // hop-2 fp32
__device__ float g_rs [(size_t)BB*NN*HH];        // r * states
__device__ float g_u  [(size_t)BB*NN*HH];        // u gate

// ------------------------- A fp32 -> bf16 -------------------------
__global__ void k_convertA(const float* __restrict__ A) {
    size_t i = ((size_t)blockIdx.x*blockDim.x + threadIdx.x)*4;
    if (i >= (size_t)NN*NN) return;
    float4 v = *(const float4*)(A + i);
    ((__nv_bfloat162*)(g_Abf + i))[0] = __float22bfloat162_rn(make_float2(v.x, v.y));
    ((__nv_bfloat162*)(g_Abf + i))[1] = __float22bfloat162_rn(make_float2(v.z, v.w));
}

// ------------------------- build X = concat(inputs, s or r*s), c = d*32+b -----------------
__global__ void k_buildX(const float* __restrict__ inputs, const float* __restrict__ st, int useRS) {
    int idx = blockIdx.x*blockDim.x + threadIdx.x;
    if (idx >= NN*CC) return;
    int n = idx / CC, c = idx % CC;
    int d = c >> 5, b = c & 31;
    float v;
    if (d < DIN)       v = inputs[((size_t)b*NN + n)*DIN + d];
    else if (useRS)    v = g_rs  [((size_t)b*NN + n)*HH  + (d-DIN)];
    else               v = st    [((size_t)b*NN + n)*HH  + (d-DIN)];
    g_Xf [idx] = v;
    g_Xbf[idx] = __float2bfloat16(v);
}

// ---- big GEMM: bf16 HMMA, CTA 256x128xBK64, warp tile 64x64, 3-stage cp.async, 1 sync/iter
// mode 0: B = g_Xbf -> g_P1f (fp32) + g_Pbf (bf16);  mode 1: B = g_Pbf -> g_P2f = 2*acc - g_Xf
__global__ __launch_bounds__(256, 1) void k_gemm(int mode)
{
    extern __shared__ char sm[];
    const int tid = threadIdx.x, lane = tid & 31, wid = tid >> 5;
    const int wm = wid >> 1, wn = wid & 1;              // 4x2 warps, 64x64 warp tile
    const int m0 = blockIdx.y*BM, c0 = blockIdx.x*BN;
    const __nv_bfloat16* __restrict__ Bq = mode ? g_Pbf : g_Xbf;
    const uint32_t sb = (uint32_t)__cvta_generic_to_shared(sm);

    float acc[4][8][4];
    #pragma unroll
    for (int i = 0; i < 4; i++)
        #pragma unroll
        for (int j = 0; j < 8; j++)
            #pragma unroll
            for (int q = 0; q < 4; q++) acc[i][j][q] = 0.f;

    auto load = [&](int kt) {
        const int k0 = kt*BK;
        const uint32_t base = sb + (kt % 3)*STG;
        #pragma unroll
        for (int qq = 0; qq < 12; qq++) {
            int i = tid + qq*256;
            const __nv_bfloat16* gp; uint32_t dst; bool ok;
            if (i < 2048) {                               // A: 256 rows x 8 16B chunks
                int r = i >> 3, ch = i & 7;
                gp  = g_Abf + (size_t)(m0 + r)*NN + k0 + ch*8;
                ok  = (m0 + r < NN) && (k0 + ch*8 < NN);
                dst = base + (uint32_t)(r*ASTRIDE + ch*8)*2;
            } else {                                      // B: 64 k-rows x 16 chunks
                int j = i - 2048, r = j >> 4, ch = j & 15;
                gp  = Bq + (size_t)(k0 + r)*CC + c0 + ch*8;
                ok  = (k0 + r < NN) && (c0 + ch*8 < CC);
                dst = base + (uint32_t)ABYTES + (uint32_t)(r*BSTRIDE + ch*8)*2;
            }
            int bytes = ok ? 16 : 0;
            if (!ok) gp = g_Abf;
            asm volatile("cp.async.cg.shared.global [%0],[%1],16,%2;"
                         :: "r"(dst), "l"(gp), "r"(bytes));
        }
        asm volatile("cp.async.commit_group;" ::: "memory");
    };

    load(0); load(1);

    for (int kt = 0; kt < KTILES; kt++) {
        asm volatile("cp.async.wait_group 1;" ::: "memory");
        __syncthreads();
        // prefetch stage kt+2 into buffer (kt+2)%3 = (kt-1)%3 (freed by the sync above)
        if (kt + 2 < KTILES) load(kt + 2);
        else asm volatile("cp.async.commit_group;" ::: "memory");

        const uint32_t aS = sb + (kt % 3)*STG;
        const uint32_t bS = aS + ABYTES;
        #pragma unroll
        for (int kk = 0; kk < 4; kk++) {
            uint32_t a[4][4];
            #pragma unroll
            for (int mt = 0; mt < 4; mt++) {
                uint32_t ad = aS + (uint32_t)((wm*64 + mt*16 + (lane & 15))*ASTRIDE
                                              + kk*16 + (lane >> 4)*8)*2;
                asm volatile("ldmatrix.sync.aligned.m8n8.x4.shared.b16 {%0,%1,%2,%3},[%4];"
                    : "=r"(a[mt][0]),"=r"(a[mt][1]),"=r"(a[mt][2]),"=r"(a[mt][3]) : "r"(ad));
            }
            uint32_t b[8][2];
            #pragma unroll
            for (int nj = 0; nj < 4; nj++) {
                uint32_t bd = bS + (uint32_t)((kk*16 + (lane & 15))*BSTRIDE
                                              + wn*64 + nj*16 + (lane >> 4)*8)*2;
                asm volatile("ldmatrix.sync.aligned.m8n8.x4.trans.shared.b16 {%0,%1,%2,%3},[%4];"
                    : "=r"(b[2*nj][0]),"=r"(b[2*nj][1]),"=r"(b[2*nj+1][0]),"=r"(b[2*nj+1][1]) : "r"(bd));
            }
            #pragma unroll
            for (int mt = 0; mt < 4; mt++)
                #pragma unroll
                for (int ni = 0; ni < 8; ni++)
                    asm volatile("mma.sync.aligned.m16n8k16.row.col.f32.bf16.bf16.f32 "
                        "{%0,%1,%2,%3},{%4,%5,%6,%7},{%8,%9},{%0,%1,%2,%3};"
                        : "+f"(acc[mt][ni][0]),"+f"(acc[mt][ni][1]),
                          "+f"(acc[mt][ni][2]),"+f"(acc[mt][ni][3])
                        : "r"(a[mt][0]),"r"(a[mt][1]),"r"(a[mt][2]),"r"(a[mt][3]),
                          "r"(b[ni][0]),"r"(b[ni][1]));
        }
    }

    // ---- epilogue ----
    float* __restrict__ outF = mode ? g_P2f : g_P1f;
    #pragma unroll
    for (int mt = 0; mt < 4; mt++)
        #pragma unroll
        for (int ni = 0; ni < 8; ni++) {
            int col = c0 + wn*64 + ni*8 + (lane & 3)*2;
            #pragma unroll
            for (int h = 0; h < 2; h++) {
                int row = m0 + wm*64 + mt*16 + (lane >> 2) + h*8;
                if (row < NN && col < CC) {
                    size_t o = (size_t)row*CC + col;
                    float v0 = acc[mt][ni][2*h], v1 = acc[mt][ni][2*h+1];
                    if (mode) {
                        v0 = 2.f*v0 - g_Xf[o];
                        v1 = 2.f*v1 - g_Xf[o+1];
                    }
                    outF[o] = v0; outF[o+1] = v1;
                    if (!mode)
                        *(__nv_bfloat162*)(g_Pbf + o) =
                            __float22bfloat162_rn(make_float2(v0, v1));
                }
            }
        }
}

// ------------------------- feature GEMM (ru): K=198 -> 128, sigmoid, r*s and u -------------
__global__ __launch_bounds__(256) void k_featRU(
    const float* __restrict__ Wru, const float* __restrict__ bru,
    const float* __restrict__ states)
{
    __shared__ float fs[KF*36];
    int n = blockIdx.x, t = threadIdx.x;
    for (int idx = t; idx < KF*BB; idx += 256) {
        int d = idx / (MHOP*BB);
        int rem = idx % (MHOP*BB);
        int m = rem >> 5, b = rem & 31;
        const float* src = (m==0)? g_Xf : (m==1)? g_P1f : g_P2f;
        fs[(d*MHOP + m)*36 + b] = src[(size_t)n*CC + d*BB + b];
    }
    __syncthreads();

    int c4 = (t & 31) * 4;
    int b4 = (t >> 5) * 4;
    float accv[4][4] = {};
    for (int k = 0; k < KF; k++) {
        float4 w = *(const float4*)(Wru + k*128 + c4);
        float4 f = *(const float4*)(&fs[k*36 + b4]);
        float wv[4] = {w.x,w.y,w.z,w.w};
        float fv[4] = {f.x,f.y,f.z,f.w};
        #pragma unroll
        for (int i=0;i<4;i++)
            #pragma unroll
            for (int j=0;j<4;j++) accv[i][j] += fv[i]*wv[j];
    }
    #pragma unroll
    for (int i=0;i<4;i++) {
        int b = b4 + i;
        #pragma unroll
        for (int j=0;j<4;j++) {
            int o = c4 + j;
            float z = accv[i][j] + bru[o];
            float s = 1.f/(1.f + __expf(-z));
            if (o < HH) {
                size_t oi = ((size_t)b*NN + n)*HH + o;
                g_rs[oi] = s * states[oi];
            } else {
                g_u[((size_t)b*NN + n)*HH + (o - HH)] = s;
            }
        }
    }
}

// ------------------------- feature GEMM (c): K=198 -> 64, tanh, final gate -----------------
__global__ __launch_bounds__(256) void k_featC(
    const float* __restrict__ Wc, const float* __restrict__ bc,
    const float* __restrict__ states, float* __restrict__ out)
{
    __shared__ float fs[KF*36];
    int n = blockIdx.x, t = threadIdx.x;
    for (int idx = t; idx < KF*BB; idx += 256) {
        int d = idx / (MHOP*BB);
        int rem = idx % (MHOP*BB);
        int m = rem >> 5, b = rem & 31;
        const float* src = (m==0)? g_Xf : (m==1)? g_P1f : g_P2f;
        fs[(d*MHOP + m)*36 + b] = src[(size_t)n*CC + d*BB + b];
    }
    __syncthreads();

    int c4 = (t & 15) * 4;
    int b2 = (t >> 4) * 2;
    float accv[2][4] = {};
    for (int k = 0; k < KF; k++) {
        float4 w = *(const float4*)(Wc + k*64 + c4);
        float2 f = *(const float2*)(&fs[k*36 + b2]);
        float wv[4] = {w.x,w.y,w.z,w.w};
        float fv[2] = {f.x,f.y};
        #pragma unroll
        for (int i=0;i<2;i++)
            #pragma unroll
            for (int j=0;j<4;j++) accv[i][j] += fv[i]*wv[j];
    }
    #pragma unroll
    for (int i=0;i<2;i++) {
        int b = b2 + i;
        #pragma unroll
        for (int j=0;j<4;j++) {
            int o = c4 + j;
            float cz = tanhf(accv[i][j] + bc[o]);
            size_t oi = ((size_t)b*NN + n)*HH + o;
            float u = g_u[oi];
            out[oi] = u*states[oi] + (1.f - u)*cz;
        }
    }
}

// ------------------------- launch -------------------------
extern "C" void kernel_launch(void* const* d_in, const int* in_sizes, int n_in,
                              void* d_out, int out_size) {
    const float* inputs = (const float*)d_in[0];
    const float* states = (const float*)d_in[1];
    const float* A      = (const float*)d_in[2];
    const float* W_ru   = (const float*)d_in[3];
    const float* b_ru   = (const float*)d_in[4];
    const float* W_c    = (const float*)d_in[5];
    const float* b_c    = (const float*)d_in[6];
    float* out = (float*)d_out;

    static int inited = 0;
    if (!inited) {
        cudaFuncSetAttribute(k_gemm, cudaFuncAttributeMaxDynamicSharedMemorySize, GSMEM);
        inited = 1;
    }

    dim3 gemmGrid((CC + BN - 1)/BN, (NN + BM - 1)/BM);   // 17 x 40

    k_convertA<<<(int)(((size_t)NN*NN/4 + 255)/256), 256>>>(A);

    // gconv 1: x = [inputs, states]
    k_buildX<<<(NN*CC + 255)/256, 256>>>(inputs, states, 0);
    k_gemm<<<gemmGrid, 256, GSMEM>>>(0);             // P1 = A @ X
    k_gemm<<<gemmGrid, 256, GSMEM>>>(1);             // P2 = 2 A @ P1 - X
    k_featRU<<<NN, 256>>>(W_ru, b_ru, states);       // sigmoid, r*s, u

    // gconv 2: x = [inputs, r*states]
    k_buildX<<<(NN*CC + 255)/256, 256>>>(inputs, states, 1);
    k_gemm<<<gemmGrid, 256, GSMEM>>>(0);             // Q1
    k_gemm<<<gemmGrid, 256, GSMEM>>>(1);             // Q2
    k_featC<<<NN, 256>>>(W_c, b_c, states, out);     // tanh + u*s + (1-u)*c
}

// round 12
// speedup vs baseline: 3.7034x; 1.1442x over previous
#include <cuda_runtime.h>
#include <cuda_bf16.h>
#include <cstdint>

#define NN   10000
#define BB   32
#define DIN  2
#define HH   64
#define GIN  66
#define CC   (GIN*BB)        // 2112
#define MHOP 3
#define KF   (GIN*MHOP)      // 198

#define BM     128
#define BN     128
#define BK     64
#define KTILES 157                 // ceil(10000/64)
#define ASTRIDE 72                 // 64 + 8 pad (bf16 elems)
#define BSTRIDE 136                // 128 + 8 pad
#define ABYTES (BM*ASTRIDE*2)      // 18432
#define STG    (ABYTES + BK*BSTRIDE*2)   // 18432 + 17408 = 35840
#define GSMEM  (3*STG)                   // 107520  (2 CTAs/SM: 215040 < 228KB)

// ------------------------- scratch (device globals; no allocation) -------------------------
__device__ __nv_bfloat16 g_Abf[(size_t)NN*NN];   // bf16 A [m][k]
__device__ __nv_bfloat16 g_Xbf[(size_t)NN*CC];   // hop-0 operand bf16 [node][c], c=d*32+b
__device__ __nv_bfloat16 g_Pbf[(size_t)NN*CC];   // hop-1 operand bf16
__device__ float g_Xf [(size_t)NN*CC];           // hop-0 fp32
__device__ float g_P1f[(size_t)NN*CC];           // hop-1 fp32
__device__ float g_P2f[(size_t)NN*CC];           // hop-2 fp32
__device__ float g_rs [(size_t)BB*NN*HH];        // r * states
__device__ float g_u  [(size_t)BB*NN*HH];        // u gate

// ------------------------- A fp32 -> bf16 -------------------------
__global__ void k_convertA(const float* __restrict__ A) {
    size_t i = ((size_t)blockIdx.x*blockDim.x + threadIdx.x)*4;
    if (i >= (size_t)NN*NN) return;
    float4 v = *(const float4*)(A + i);
    ((__nv_bfloat162*)(g_Abf + i))[0] = __float22bfloat162_rn(make_float2(v.x, v.y));
    ((__nv_bfloat162*)(g_Abf + i))[1] = __float22bfloat162_rn(make_float2(v.z, v.w));
}

// ------------------------- build X = concat(inputs, s or r*s), c = d*32+b -----------------
__global__ void k_buildX(const float* __restrict__ inputs, const float* __restrict__ st, int useRS) {
    int idx = blockIdx.x*blockDim.x + threadIdx.x;
    if (idx >= NN*CC) return;
    int n = idx / CC, c = idx % CC;
    int d = c >> 5, b = c & 31;
    float v;
    if (d < DIN)       v = inputs[((size_t)b*NN + n)*DIN + d];
    else if (useRS)    v = g_rs  [((size_t)b*NN + n)*HH  + (d-DIN)];
    else               v = st    [((size_t)b*NN + n)*HH  + (d-DIN)];
    g_Xf [idx] = v;
    g_Xbf[idx] = __float2bfloat16(v);
}

// ---- big GEMM: bf16 HMMA, CTA 128x128xBK64, warp tile 32x64, 3-stage, 2 CTAs/SM ----------
// mode 0: B = g_Xbf -> g_P1f (fp32) + g_Pbf (bf16);  mode 1: B = g_Pbf -> g_P2f = 2*acc - g_Xf
__global__ __launch_bounds__(256, 2) void k_gemm(int mode)
{
    extern __shared__ char sm[];
    const int tid = threadIdx.x, lane = tid & 31, wid = tid >> 5;
    const int wm = wid >> 1, wn = wid & 1;              // 4x2 warps, 32x64 warp tile
    const int m0 = blockIdx.y*BM, c0 = blockIdx.x*BN;
    const __nv_bfloat16* __restrict__ Bq = mode ? g_Pbf : g_Xbf;
    const uint32_t sb = (uint32_t)__cvta_generic_to_shared(sm);

    float acc[2][8][4];
    #pragma unroll
    for (int i = 0; i < 2; i++)
        #pragma unroll
        for (int j = 0; j < 8; j++)
            #pragma unroll
            for (int q = 0; q < 4; q++) acc[i][j][q] = 0.f;

    auto load = [&](int kt) {
        const int k0 = kt*BK;
        const uint32_t base = sb + (kt % 3)*STG;
        #pragma unroll
        for (int qq = 0; qq < 8; qq++) {
            int i = tid + qq*256;
            const __nv_bfloat16* gp; uint32_t dst; bool ok;
            if (i < 1024) {                               // A: 128 rows x 8 16B chunks
                int r = i >> 3, ch = i & 7;
                gp  = g_Abf + (size_t)(m0 + r)*NN + k0 + ch*8;
                ok  = (m0 + r < NN) && (k0 + ch*8 < NN);
                dst = base + (uint32_t)(r*ASTRIDE + ch*8)*2;
            } else {                                      // B: 64 k-rows x 16 chunks
                int j = i - 1024, r = j >> 4, ch = j & 15;
                gp  = Bq + (size_t)(k0 + r)*CC + c0 + ch*8;
                ok  = (k0 + r < NN) && (c0 + ch*8 < CC);
                dst = base + (uint32_t)ABYTES + (uint32_t)(r*BSTRIDE + ch*8)*2;
            }
            int bytes = ok ? 16 : 0;
            if (!ok) gp = g_Abf;
            asm volatile("cp.async.cg.shared.global [%0],[%1],16,%2;"
                         :: "r"(dst), "l"(gp), "r"(bytes));
        }
        asm volatile("cp.async.commit_group;" ::: "memory");
    };

    load(0); load(1);

    for (int kt = 0; kt < KTILES; kt++) {
        asm volatile("cp.async.wait_group 1;" ::: "memory");
        __syncthreads();
        // prefetch stage kt+2 into buffer (kt+2)%3 = (kt-1)%3 (freed by the sync above)
        if (kt + 2 < KTILES) load(kt + 2);
        else asm volatile("cp.async.commit_group;" ::: "memory");

        const uint32_t aS = sb + (kt % 3)*STG;
        const uint32_t bS = aS + ABYTES;
        #pragma unroll
        for (int kk = 0; kk < 4; kk++) {
            uint32_t a[2][4];
            #pragma unroll
            for (int mt = 0; mt < 2; mt++) {
                uint32_t ad = aS + (uint32_t)((wm*32 + mt*16 + (lane & 15))*ASTRIDE
                                              + kk*16 + (lane >> 4)*8)*2;
                asm volatile("ldmatrix.sync.aligned.m8n8.x4.shared.b16 {%0,%1,%2,%3},[%4];"
                    : "=r"(a[mt][0]),"=r"(a[mt][1]),"=r"(a[mt][2]),"=r"(a[mt][3]) : "r"(ad));
            }
            uint32_t b[8][2];
            #pragma unroll
            for (int nj = 0; nj < 4; nj++) {
                uint32_t bd = bS + (uint32_t)((kk*16 + (lane & 15))*BSTRIDE
                                              + wn*64 + nj*16 + (lane >> 4)*8)*2;
                asm volatile("ldmatrix.sync.aligned.m8n8.x4.trans.shared.b16 {%0,%1,%2,%3},[%4];"
                    : "=r"(b[2*nj][0]),"=r"(b[2*nj][1]),"=r"(b[2*nj+1][0]),"=r"(b[2*nj+1][1]) : "r"(bd));
            }
            #pragma unroll
            for (int mt = 0; mt < 2; mt++)
                #pragma unroll
                for (int ni = 0; ni < 8; ni++)
                    asm volatile("mma.sync.aligned.m16n8k16.row.col.f32.bf16.bf16.f32 "
                        "{%0,%1,%2,%3},{%4,%5,%6,%7},{%8,%9},{%0,%1,%2,%3};"
                        : "+f"(acc[mt][ni][0]),"+f"(acc[mt][ni][1]),
                          "+f"(acc[mt][ni][2]),"+f"(acc[mt][ni][3])
                        : "r"(a[mt][0]),"r"(a[mt][1]),"r"(a[mt][2]),"r"(a[mt][3]),
                          "r"(b[ni][0]),"r"(b[ni][1]));
        }
    }

    // ---- epilogue ----
    float* __restrict__ outF = mode ? g_P2f : g_P1f;
    #pragma unroll
    for (int mt = 0; mt < 2; mt++)
        #pragma unroll
        for (int ni = 0; ni < 8; ni++) {
            int col = c0 + wn*64 + ni*8 + (lane & 3)*2;
            #pragma unroll
            for (int h = 0; h < 2; h++) {
                int row = m0 + wm*32 + mt*16 + (lane >> 2) + h*8;
                if (row < NN && col < CC) {
                    size_t o = (size_t)row*CC + col;
                    float v0 = acc[mt][ni][2*h], v1 = acc[mt][ni][2*h+1];
                    if (mode) {
                        v0 = 2.f*v0 - g_Xf[o];
                        v1 = 2.f*v1 - g_Xf[o+1];
                    }
                    outF[o] = v0; outF[o+1] = v1;
                    if (!mode)
                        *(__nv_bfloat162*)(g_Pbf + o) =
                            __float22bfloat162_rn(make_float2(v0, v1));
                }
            }
        }
}

// ------------------------- feature GEMM (ru): K=198 -> 128, sigmoid, r*s and u -------------
__global__ __launch_bounds__(256) void k_featRU(
    const float* __restrict__ Wru, const float* __restrict__ bru,
    const float* __restrict__ states)
{
    __shared__ float fs[KF*36];
    int n = blockIdx.x, t = threadIdx.x;
    for (int idx = t; idx < KF*BB; idx += 256) {
        int d = idx / (MHOP*BB);
        int rem = idx % (MHOP*BB);
        int m = rem >> 5, b = rem & 31;
        const float* src = (m==0)? g_Xf : (m==1)? g_P1f : g_P2f;
        fs[(d*MHOP + m)*36 + b] = src[(size_t)n*CC + d*BB + b];
    }
    __syncthreads();

    int c4 = (t & 31) * 4;
    int b4 = (t >> 5) * 4;
    float accv[4][4] = {};
    for (int k = 0; k < KF; k++) {
        float4 w = *(const float4*)(Wru + k*128 + c4);
        float4 f = *(const float4*)(&fs[k*36 + b4]);
        float wv[4] = {w.x,w.y,w.z,w.w};
        float fv[4] = {f.x,f.y,f.z,f.w};
        #pragma unroll
        for (int i=0;i<4;i++)
            #pragma unroll
            for (int j=0;j<4;j++) accv[i][j] += fv[i]*wv[j];
    }
    #pragma unroll
    for (int i=0;i<4;i++) {
        int b = b4 + i;
        #pragma unroll
        for (int j=0;j<4;j++) {
            int o = c4 + j;
            float z = accv[i][j] + bru[o];
            float s = 1.f/(1.f + __expf(-z));
            if (o < HH) {
                size_t oi = ((size_t)b*NN + n)*HH + o;
                g_rs[oi] = s * states[oi];
            } else {
                g_u[((size_t)b*NN + n)*HH + (o - HH)] = s;
            }
        }
    }
}

// ------------------------- feature GEMM (c): K=198 -> 64, tanh, final gate -----------------
__global__ __launch_bounds__(256) void k_featC(
    const float* __restrict__ Wc, const float* __restrict__ bc,
    const float* __restrict__ states, float* __restrict__ out)
{
    __shared__ float fs[KF*36];
    int n = blockIdx.x, t = threadIdx.x;
    for (int idx = t; idx < KF*BB; idx += 256) {
        int d = idx / (MHOP*BB);
        int rem = idx % (MHOP*BB);
        int m = rem >> 5, b = rem & 31;
        const float* src = (m==0)? g_Xf : (m==1)? g_P1f : g_P2f;
        fs[(d*MHOP + m)*36 + b] = src[(size_t)n*CC + d*BB + b];
    }
    __syncthreads();

    int c4 = (t & 15) * 4;
    int b2 = (t >> 4) * 2;
    float accv[2][4] = {};
    for (int k = 0; k < KF; k++) {
        float4 w = *(const float4*)(Wc + k*64 + c4);
        float2 f = *(const float2*)(&fs[k*36 + b2]);
        float wv[4] = {w.x,w.y,w.z,w.w};
        float fv[2] = {f.x,f.y};
        #pragma unroll
        for (int i=0;i<2;i++)
            #pragma unroll
            for (int j=0;j<4;j++) accv[i][j] += fv[i]*wv[j];
    }
    #pragma unroll
    for (int i=0;i<2;i++) {
        int b = b2 + i;
        #pragma unroll
        for (int j=0;j<4;j++) {
            int o = c4 + j;
            float cz = tanhf(accv[i][j] + bc[o]);
            size_t oi = ((size_t)b*NN + n)*HH + o;
            float u = g_u[oi];
            out[oi] = u*states[oi] + (1.f - u)*cz;
        }
    }
}

// ------------------------- launch -------------------------
extern "C" void kernel_launch(void* const* d_in, const int* in_sizes, int n_in,
                              void* d_out, int out_size) {
    const float* inputs = (const float*)d_in[0];
    const float* states = (const float*)d_in[1];
    const float* A      = (const float*)d_in[2];
    const float* W_ru   = (const float*)d_in[3];
    const float* b_ru   = (const float*)d_in[4];
    const float* W_c    = (const float*)d_in[5];
    const float* b_c    = (const float*)d_in[6];
    float* out = (float*)d_out;

    static int inited = 0;
    if (!inited) {
        cudaFuncSetAttribute(k_gemm, cudaFuncAttributeMaxDynamicSharedMemorySize, GSMEM);
        inited = 1;
    }

    dim3 gemmGrid((CC + BN - 1)/BN, (NN + BM - 1)/BM);   // 17 x 79

    k_convertA<<<(int)(((size_t)NN*NN/4 + 255)/256), 256>>>(A);

    // gconv 1: x = [inputs, states]
    k_buildX<<<(NN*CC + 255)/256, 256>>>(inputs, states, 0);
    k_gemm<<<gemmGrid, 256, GSMEM>>>(0);             // P1 = A @ X
    k_gemm<<<gemmGrid, 256, GSMEM>>>(1);             // P2 = 2 A @ P1 - X
    k_featRU<<<NN, 256>>>(W_ru, b_ru, states);       // sigmoid, r*s, u

    // gconv 2: x = [inputs, r*states]
    k_buildX<<<(NN*CC + 255)/256, 256>>>(inputs, states, 1);
    k_gemm<<<gemmGrid, 256, GSMEM>>>(0);             // Q1
    k_gemm<<<gemmGrid, 256, GSMEM>>>(1);             // Q2
    k_featC<<<NN, 256>>>(W_c, b_c, states, out);     // tanh + u*s + (1-u)*c
}